// round 6
// baseline (speedup 1.0000x reference)
#include <cuda_runtime.h>
#include <cuda_bf16.h>
#include <cstdint>

// Depthwise separable Gaussian blur, K=121, replicate padding.
// out = (x *row g1d) *col g1d; g1d = normalized 1D Gaussian (exact separation
// of the reference's normalized 2D kernel).
// Both passes use packed fma.rn.f32x2 (pair axis perpendicular to conv axis).
// Weights are computed redundantly per block (no prep kernel).

#define IMGS   24          // 8 * 3
#define HW     512
#define IMG_PX (HW * HW)   // 262144
#define TAPS   121
#define TPAD   128         // taps padded with zeros to 128

__device__ float g_tmp[IMGS * IMG_PX];      // horizontal-pass scratch (~25 MB)

// Compute normalized 1D weights into wsh[TPAD] (zero-padded). 64 threads.
// Caller must __syncthreads() before reading wsh.
__device__ __forceinline__ void compute_weights(const float* __restrict__ sigma,
                                                float* wsh, float* wsum2) {
    const int t = threadIdx.x & 63;
    const float s    = sigma[0] * 8.0f + 16.0f;
    const float inv2v = 1.0f / (2.0f * s * s);
    // tap t (always < 121) and tap t+64 (valid when t < 57)
    const float da = (float)(t - 60);
    const float va = expf(-(da * da) * inv2v);
    float vb = 0.0f;
    if (t + 64 < TAPS) {
        const float db = (float)(t + 4);   // (t+64) - 60
        vb = expf(-(db * db) * inv2v);
    }
    float part = va + vb;
    #pragma unroll
    for (int off = 16; off; off >>= 1)
        part += __shfl_xor_sync(0xffffffffu, part, off);
    if ((threadIdx.x & 31) == 0) wsum2[threadIdx.x >> 5] = part;
    __syncthreads();
    const float inv = 1.0f / (wsum2[0] + wsum2[1]);
    wsh[t]      = va * inv;
    wsh[t + 64] = vb * inv;   // zero for padded taps
}

// ---------------------------------------------------------------------------
// Pass 1: horizontal 121-tap conv, f32x2 over a ROW PAIR.
// One block per (img, row-pair); 64 threads; each lane computes 8 consecutive
// x outputs for both rows via a 16-deep f32x2 register ring.
// smem: interleaved row pair irow[i] = {row0[clamp(i-60)], row1[clamp(i-60)]}.
// ---------------------------------------------------------------------------
#define ROWLEN 656   // 60 halo + 512 + padded tail (ring reads up to idx 647)

__global__ __launch_bounds__(64) void hpass_kernel(const float* __restrict__ x,
                                                   const float* __restrict__ sigma) {
    __shared__ float2 srow[ROWLEN];
    __shared__ float  wsh[TPAD];
    __shared__ float  wsum2[2];
    const int t    = threadIdx.x;
    const int rp   = blockIdx.x;        // row pair 0..255
    const int img  = blockIdx.y;
    const float* s0 = x + ((size_t)img * HW + rp * 2) * HW;
    const float* s1 = s0 + HW;

    compute_weights(sigma, wsh, wsum2);

    #pragma unroll
    for (int i = t; i < ROWLEN; i += 64) {
        int xi = i - 60;
        xi = xi < 0 ? 0 : (xi > HW - 1 ? HW - 1 : xi);
        srow[i] = make_float2(s0[xi], s1[xi]);
    }
    __syncthreads();

    const int x0 = t * 8;
    const unsigned long long* srow2 = (const unsigned long long*)srow;

    unsigned long long buf[16];
    #pragma unroll
    for (int q = 0; q < 16; ++q) buf[q] = srow2[x0 + q];
    unsigned long long acc[8];
    #pragma unroll
    for (int j = 0; j < 8; ++j) acc[j] = 0ULL;

    #pragma unroll 1
    for (int kb = 0; kb < 8; ++kb) {          // 8 x 16 = 128 taps (zero-padded)
        #pragma unroll
        for (int i = 0; i < 16; ++i) {
            const int k = kb * 16 + i;
            const float wk = wsh[k];
            unsigned long long w2;
            asm("mov.b64 %0, {%1, %1};" : "=l"(w2) : "f"(wk));
            #pragma unroll
            for (int j = 0; j < 8; ++j)
                asm("fma.rn.f32x2 %0, %1, %2, %0;"
                    : "+l"(acc[j]) : "l"(buf[(i + j) & 15]), "l"(w2));
            buf[i] = srow2[x0 + k + 16];       // slide window
        }
    }

    // de-interleave and store both rows as float4
    float lo[8], hi[8];
    #pragma unroll
    for (int j = 0; j < 8; ++j) {
        lo[j] = __uint_as_float((unsigned)(acc[j] & 0xffffffffu));
        hi[j] = __uint_as_float((unsigned)(acc[j] >> 32));
    }
    float* d0 = g_tmp + ((size_t)img * HW + rp * 2) * HW + x0;
    float* d1 = d0 + HW;
    ((float4*)d0)[0] = make_float4(lo[0], lo[1], lo[2], lo[3]);
    ((float4*)d0)[1] = make_float4(lo[4], lo[5], lo[6], lo[7]);
    ((float4*)d1)[0] = make_float4(hi[0], hi[1], hi[2], hi[3]);
    ((float4*)d1)[1] = make_float4(hi[4], hi[5], hi[6], hi[7]);
}

// ---------------------------------------------------------------------------
// Pass 2: vertical 121-tap conv with f32x2 (2 x-columns per lane).
// Block: 32-col x 64-row output tile, 64 threads = 16 x-pairs x 4 y-groups,
// each thread computes 16 y outputs for its x-pair (16-deep f32x2 ring).
// smem tile: 192 rows x 32 cols (60 top halo + 64 + padded bottom).
// ---------------------------------------------------------------------------
#define TROWS 192
#define TCOLS 32

__global__ __launch_bounds__(64) void vpass_kernel(float* __restrict__ out,
                                                   const float* __restrict__ sigma) {
    __shared__ float tile[TROWS * TCOLS];
    __shared__ float wsh[TPAD];
    __shared__ float wsum2[2];
    const int t     = threadIdx.x;
    const int img   = blockIdx.z;
    const int xbase = blockIdx.x * TCOLS;
    const int ybase = blockIdx.y * 64;
    const float* src = g_tmp + (size_t)img * IMG_PX;

    compute_weights(sigma, wsh, wsum2);

    // stage 192x32 tile (coalesced float4 rows, replicate-clamped in y)
    const int cx4 = t & 7;     // float4 column 0..7
    const int r0  = t >> 3;    // 0..7
    #pragma unroll
    for (int rr = 0; rr < TROWS; rr += 8) {
        const int r = rr + r0;
        int gy = ybase - 60 + r;
        gy = gy < 0 ? 0 : (gy > HW - 1 ? HW - 1 : gy);
        float4 v = ((const float4*)(src + (size_t)gy * HW + xbase))[cx4];
        ((float4*)tile)[r * 8 + cx4] = v;
    }
    __syncthreads();

    const int px = t & 15;          // x-pair 0..15 -> cols 2*px, 2*px+1
    const int yg = (t >> 4) * 16;   // y-group base: 0,16,32,48
    const unsigned long long* tile2 = (const unsigned long long*)tile; // 16 pairs/row

    unsigned long long buf[16];
    #pragma unroll
    for (int q = 0; q < 16; ++q) buf[q] = tile2[(yg + q) * 16 + px];
    unsigned long long acc[16];
    #pragma unroll
    for (int j = 0; j < 16; ++j) acc[j] = 0ULL;

    #pragma unroll 1
    for (int kb = 0; kb < 8; ++kb) {
        #pragma unroll
        for (int i = 0; i < 16; ++i) {
            const int k = kb * 16 + i;
            const float wk = wsh[k];
            unsigned long long w2;
            asm("mov.b64 %0, {%1, %1};" : "=l"(w2) : "f"(wk));
            #pragma unroll
            for (int j = 0; j < 16; ++j)
                asm("fma.rn.f32x2 %0, %1, %2, %0;"
                    : "+l"(acc[j]) : "l"(buf[(i + j) & 15]), "l"(w2));
            buf[i] = tile2[(yg + k + 16) * 16 + px];   // slide window
        }
    }

    float* dstbase = out + (size_t)img * IMG_PX
                   + (size_t)(ybase + yg) * HW + xbase + px * 2;
    #pragma unroll
    for (int j = 0; j < 16; ++j) {
        const unsigned long long a = acc[j];
        float2 o;
        o.x = __uint_as_float((unsigned)(a & 0xffffffffu));
        o.y = __uint_as_float((unsigned)(a >> 32));
        *((float2*)(dstbase + (size_t)j * HW)) = o;
    }
}

// ---------------------------------------------------------------------------
extern "C" void kernel_launch(void* const* d_in, const int* in_sizes, int n_in,
                              void* d_out, int out_size) {
    const float* x     = (const float*)d_in[0];
    const float* sigma = (const float*)d_in[1];
    float* out = (float*)d_out;

    hpass_kernel<<<dim3(HW / 2, IMGS), 64>>>(x, sigma);
    vpass_kernel<<<dim3(HW / TCOLS, HW / 64, IMGS), 64>>>(out, sigma);
}

// round 11
// speedup vs baseline: 1.0136x; 1.0136x over previous
#include <cuda_runtime.h>
#include <cuda_bf16.h>
#include <cstdint>

// Depthwise separable Gaussian blur, K=121, replicate padding.
// out = (x *row g1d) *col g1d; g1d = normalized 1D Gaussian (exact separation
// of the reference's normalized 2D kernel).
// Both passes use packed fma.rn.f32x2 with identical conflict-free ring
// structure: ring smem index = i*16 + pairlane (lane-consecutive).
// Weights pre-packed {w,w} in smem + register-prefetched 2 taps ahead.

#define IMGS   24          // 8 * 3
#define HW     512
#define IMG_PX (HW * HW)   // 262144
#define TAPS   121
#define WPAD   132         // packed weights padded (prefetch reads up to [129])

__device__ float g_tmp[IMGS * IMG_PX];      // horizontal-pass scratch (~25 MB)

// Compute normalized 1D weights pre-packed as {w,w} into wsh2[WPAD].
// 64 threads; caller must __syncthreads() before reading wsh2.
__device__ __forceinline__ void compute_weights(const float* __restrict__ sigma,
                                                float2* wsh2, float* wsum2) {
    const int t = threadIdx.x;  // 0..63
    const float s     = sigma[0] * 8.0f + 16.0f;
    const float inv2v = 1.0f / (2.0f * s * s);
    const float da = (float)(t - 60);
    const float va = expf(-(da * da) * inv2v);
    float vb = 0.0f;
    if (t + 64 < TAPS) {
        const float db = (float)(t + 4);   // (t+64) - 60
        vb = expf(-(db * db) * inv2v);
    }
    float part = va + vb;
    #pragma unroll
    for (int off = 16; off; off >>= 1)
        part += __shfl_xor_sync(0xffffffffu, part, off);
    if ((t & 31) == 0) wsum2[t >> 5] = part;
    __syncthreads();
    const float inv = 1.0f / (wsum2[0] + wsum2[1]);
    const float wa = va * inv;
    const float wb = vb * inv;          // 0 for padded taps 121..127
    wsh2[t]      = make_float2(wa, wa);
    wsh2[t + 64] = make_float2(wb, wb);
    if (t < 4) wsh2[128 + t] = make_float2(0.0f, 0.0f);
}

// ---------------------------------------------------------------------------
// Pass 1: horizontal 121-tap conv. Block tile: 64 x-outputs x 32 y-rows.
// smem tile: 192 x-positions x 16 y-pairs, tile2[i*16+py] = {row2py, row2py+1}
// at global x = clamp(xbase-60+i). Ring slides along i (x). 64 threads =
// 16 y-pairs x 4 x-groups; each thread: 16 x-outputs for its y-pair.
// ---------------------------------------------------------------------------
__global__ __launch_bounds__(64) void hpass_kernel(const float* __restrict__ x,
                                                   const float* __restrict__ sigma) {
    __shared__ float2 tile[192 * 16];
    __shared__ float2 wsh2[WPAD];
    __shared__ float  wsum2[2];
    const int t     = threadIdx.x;
    const int img   = blockIdx.z;
    const int xbase = blockIdx.x * 64;
    const int ybase = blockIdx.y * 32;

    compute_weights(sigma, wsh2, wsum2);

    // Staging: thread (y = t&31, xh = t>>5) fills its half of the i-range for
    // its row. smem word index = i*32 + y -> bank = y%32: conflict-free.
    {
        const int y  = t & 31;
        const int xh = t >> 5;
        const float* srcrow = x + ((size_t)img * HW + (ybase + y)) * HW;
        float* tf = (float*)tile;
        const int wbase = (t & 1) + ((t & 31) >> 1) * 2;  // == y, kept explicit
        #pragma unroll 4
        for (int q = 0; q < 96; ++q) {
            const int i = xh * 96 + q;
            int gx = xbase - 60 + i;
            gx = gx < 0 ? 0 : (gx > HW - 1 ? HW - 1 : gx);
            tf[i * 32 + wbase] = srcrow[gx];
        }
    }
    __syncthreads();

    const int pg = t & 15;          // y-pair 0..15 -> rows ybase+2pg, +1
    const int xg = (t >> 4) * 16;   // x-output group base: 0,16,32,48
    const unsigned long long* tile2 = (const unsigned long long*)tile;
    const unsigned long long* wshu  = (const unsigned long long*)wsh2;

    unsigned long long buf[16];
    #pragma unroll
    for (int q = 0; q < 16; ++q) buf[q] = tile2[(xg + q) * 16 + pg];
    unsigned long long acc[16];
    #pragma unroll
    for (int j = 0; j < 16; ++j) acc[j] = 0ULL;

    unsigned long long wcur = wshu[0], wnxt = wshu[1];
    #pragma unroll 1
    for (int kb = 0; kb < 8; ++kb) {          // 8 x 16 = 128 taps (zero-padded)
        #pragma unroll
        for (int i = 0; i < 16; ++i) {
            const int k = kb * 16 + i;
            const unsigned long long w2 = wcur;
            wcur = wnxt;
            wnxt = wshu[k + 2];
            #pragma unroll
            for (int j = 0; j < 16; ++j)
                asm("fma.rn.f32x2 %0, %1, %2, %0;"
                    : "+l"(acc[j]) : "l"(buf[(i + j) & 15]), "l"(w2));
            buf[i] = tile2[(xg + k + 16) * 16 + pg];   // slide window
        }
    }

    // de-interleave: acc[j] = {row 2pg, row 2pg+1} at x = xbase+xg+j
    float lo[16], hi[16];
    #pragma unroll
    for (int j = 0; j < 16; ++j) {
        lo[j] = __uint_as_float((unsigned)(acc[j] & 0xffffffffu));
        hi[j] = __uint_as_float((unsigned)(acc[j] >> 32));
    }
    float* d0 = g_tmp + ((size_t)img * HW + (ybase + 2 * pg)) * HW + xbase + xg;
    float* d1 = d0 + HW;
    #pragma unroll
    for (int q = 0; q < 4; ++q) {
        ((float4*)d0)[q] = make_float4(lo[q*4+0], lo[q*4+1], lo[q*4+2], lo[q*4+3]);
        ((float4*)d1)[q] = make_float4(hi[q*4+0], hi[q*4+1], hi[q*4+2], hi[q*4+3]);
    }
}

// ---------------------------------------------------------------------------
// Pass 2: vertical 121-tap conv. Block tile: 32 cols x 64 rows.
// smem tile: 192 rows x 32 cols (60 top halo + 64 + padded bottom), read as
// 16 x-pairs per row. 64 threads = 16 x-pairs x 4 y-groups; each thread:
// 16 y-outputs for its x-pair.
// ---------------------------------------------------------------------------
__global__ __launch_bounds__(64) void vpass_kernel(float* __restrict__ out,
                                                   const float* __restrict__ sigma) {
    __shared__ float  tile[192 * 32];
    __shared__ float2 wsh2[WPAD];
    __shared__ float  wsum2[2];
    const int t     = threadIdx.x;
    const int img   = blockIdx.z;
    const int xbase = blockIdx.x * 32;
    const int ybase = blockIdx.y * 64;
    const float* src = g_tmp + (size_t)img * IMG_PX;

    compute_weights(sigma, wsh2, wsum2);

    // stage 192x32 tile (coalesced float4 rows, replicate-clamped in y)
    const int cx4 = t & 7;     // float4 column 0..7
    const int r0  = t >> 3;    // 0..7
    #pragma unroll
    for (int rr = 0; rr < 192; rr += 8) {
        const int r = rr + r0;
        int gy = ybase - 60 + r;
        gy = gy < 0 ? 0 : (gy > HW - 1 ? HW - 1 : gy);
        float4 v = ((const float4*)(src + (size_t)gy * HW + xbase))[cx4];
        ((float4*)tile)[r * 8 + cx4] = v;
    }
    __syncthreads();

    const int px = t & 15;          // x-pair 0..15 -> cols 2*px, 2*px+1
    const int yg = (t >> 4) * 16;   // y-group base: 0,16,32,48
    const unsigned long long* tile2 = (const unsigned long long*)tile;
    const unsigned long long* wshu  = (const unsigned long long*)wsh2;

    unsigned long long buf[16];
    #pragma unroll
    for (int q = 0; q < 16; ++q) buf[q] = tile2[(yg + q) * 16 + px];
    unsigned long long acc[16];
    #pragma unroll
    for (int j = 0; j < 16; ++j) acc[j] = 0ULL;

    unsigned long long wcur = wshu[0], wnxt = wshu[1];
    #pragma unroll 1
    for (int kb = 0; kb < 8; ++kb) {
        #pragma unroll
        for (int i = 0; i < 16; ++i) {
            const int k = kb * 16 + i;
            const unsigned long long w2 = wcur;
            wcur = wnxt;
            wnxt = wshu[k + 2];
            #pragma unroll
            for (int j = 0; j < 16; ++j)
                asm("fma.rn.f32x2 %0, %1, %2, %0;"
                    : "+l"(acc[j]) : "l"(buf[(i + j) & 15]), "l"(w2));
            buf[i] = tile2[(yg + k + 16) * 16 + px];   // slide window
        }
    }

    float* dstbase = out + (size_t)img * IMG_PX
                   + (size_t)(ybase + yg) * HW + xbase + px * 2;
    #pragma unroll
    for (int j = 0; j < 16; ++j) {
        const unsigned long long a = acc[j];
        float2 o;
        o.x = __uint_as_float((unsigned)(a & 0xffffffffu));
        o.y = __uint_as_float((unsigned)(a >> 32));
        *((float2*)(dstbase + (size_t)j * HW)) = o;
    }
}

// ---------------------------------------------------------------------------
extern "C" void kernel_launch(void* const* d_in, const int* in_sizes, int n_in,
                              void* d_out, int out_size) {
    const float* x     = (const float*)d_in[0];
    const float* sigma = (const float*)d_in[1];
    float* out = (float*)d_out;

    hpass_kernel<<<dim3(HW / 64, HW / 32, IMGS), 64>>>(x, sigma);
    vpass_kernel<<<dim3(HW / 32, HW / 64, IMGS), 64>>>(out, sigma);
}